// round 14
// baseline (speedup 1.0000x reference)
#include <cuda_runtime.h>
#include <cuda_bf16.h>
#include <math.h>

#define HID 128
#define OUT 128
#define NMAX 50000
#define ESTRIDE 324   // node input stride (floats)
#define HSTRIDE 132   // node hidden stride
#define TILE 64       // node tile
#define ETILE 128     // edge tile (rows per block)
#define ETHREADS 512
#define TWORDS 512    // uint4 per weight tile
#define EP2 164       // edge A stride in uint2 (2*164 % 32 == 8 -> conflict-free LDS.64)

// ---------------- device scratch (no allocations anywhere) ----------------
__device__ float g_aggr[(size_t)NMAX * OUT];
__device__ float g_xsum[(size_t)NMAX * 3];
__device__ float g_cnt[NMAX];

// Fused-fragment weights: per tile/col/tg -> uint4{bh0,bh1,bl0,bl1}
__device__ uint4 g_eW1p[19 * TWORDS];
__device__ uint4 g_eW2p[8 * TWORDS];
__device__ uint4 g_cW1p[8 * TWORDS];
__device__ uint4 g_nW1p[20 * TWORDS];
__device__ uint4 g_nW2p[8 * TWORDS];

__device__ __forceinline__ float lrelu(float v) { return v > 0.f ? v : 0.01f * v; }

// ---------------- bf16 split helpers ----------------
__device__ __forceinline__ unsigned bf16x2_pack(float a, float b) {
    unsigned r;
    asm("cvt.rn.bf16x2.f32 %0, %1, %2;" : "=r"(r) : "f"(b), "f"(a));
    return r;
}
__device__ __forceinline__ float bf16_lo_f(unsigned p) { return __uint_as_float(p << 16); }
__device__ __forceinline__ float bf16_hi_f(unsigned p) { return __uint_as_float(p & 0xffff0000u); }
__device__ __forceinline__ void split2(float2 a, unsigned& hi, unsigned& lo) {
    hi = bf16x2_pack(a.x, a.y);
    lo = bf16x2_pack(a.x - bf16_lo_f(hi), a.y - bf16_hi_f(hi));
}

// m16n8k16 bf16 MMA, C += A*B
__device__ __forceinline__ void mma16(float c[4], const unsigned a[4], unsigned b0, unsigned b1) {
    asm("mma.sync.aligned.m16n8k16.row.col.f32.bf16.bf16.f32 "
        "{%0,%1,%2,%3}, {%4,%5,%6,%7}, {%8,%9}, {%0,%1,%2,%3};"
        : "+f"(c[0]), "+f"(c[1]), "+f"(c[2]), "+f"(c[3])
        : "r"(a[0]), "r"(a[1]), "r"(a[2]), "r"(a[3]), "r"(b0), "r"(b1));
}

__device__ __forceinline__ void red_v4(float* addr, float4 v) {
    asm volatile("red.global.add.v4.f32 [%0], {%1,%2,%3,%4};"
                 :: "l"(addr), "f"(v.x), "f"(v.y), "f"(v.z), "f"(v.w) : "memory");
}

// ---------------- prepack kernel: fp32 weights -> fused uint4 fragments -----
__device__ __forceinline__ float wval(const float* W, int k, int col, int krows, bool remap) {
    if (k >= krows) return 0.f;
    int kr = (remap && k >= 256) ? k + 128 : k;
    return W[(size_t)kr * 128 + col];
}

__global__ void prepack_kernel(const float* __restrict__ eW1, const float* __restrict__ eW2,
                               const float* __restrict__ cW1, const float* __restrict__ nW1,
                               const float* __restrict__ nW2)
{
    int idx = blockIdx.x * 256 + threadIdx.x;
    if (idx >= 63 * TWORDS) return;
    int within = idx & (TWORDS - 1);
    int gt = idx >> 9;
    int col = within >> 2, tg = within & 3;

    const float* W; uint4* Out; int lt, krows; bool remap = false;
    if (gt < 19)      { W = eW1; Out = g_eW1p; lt = gt;      krows = 303; }
    else if (gt < 27) { W = eW2; Out = g_eW2p; lt = gt - 19; krows = 128; }
    else if (gt < 35) { W = cW1; Out = g_cW1p; lt = gt - 27; krows = 128; }
    else if (gt < 55) { W = nW1; Out = g_nW1p; lt = gt - 35; krows = 320; remap = true; }
    else              { W = nW2; Out = g_nW2p; lt = gt - 55; krows = 128; }

    int k0 = (lt * 8 + tg) * 2;
    int k2 = (lt * 8 + tg + 4) * 2;
    float a0 = wval(W, k0, col, krows, remap), a1 = wval(W, k0 + 1, col, krows, remap);
    float a2 = wval(W, k2, col, krows, remap), a3 = wval(W, k2 + 1, col, krows, remap);

    unsigned h0 = bf16x2_pack(a0, a1);
    unsigned h1 = bf16x2_pack(a2, a3);
    unsigned l0 = bf16x2_pack(a0 - bf16_lo_f(h0), a1 - bf16_hi_f(h0));
    unsigned l1 = bf16x2_pack(a2 - bf16_lo_f(h1), a3 - bf16_hi_f(h1));
    Out[lt * TWORDS + within] = make_uint4(h0, h1, l0, l1);
}

// ---------------- edge GEMM (512 threads): packed-A + fused uint4 B ---------
__device__ __forceinline__ void gemm_pk(const uint2* __restrict__ ea, int abase,
                                        const uint4* __restrict__ Wp, int ntiles,
                                        uint4* __restrict__ wb,
                                        int tid, int r1, int cbase, int gid, int tg,
                                        float c[8][4])
{
    uint4 w0 = Wp[tid];
    const uint2* Ar1 = ea + (size_t)r1 * EP2 + abase;
    const uint2* Ar2 = Ar1 + 8 * EP2;
    __syncthreads();                      // prior consumers of wb / producers of ea done
    wb[tid] = w0;
    if (ntiles > 1) w0 = Wp[TWORDS + tid];
#pragma unroll 1
    for (int t = 0; t < ntiles; ++t) {
        __syncthreads();                  // tile t visible; all warps done with tile t-1
        const uint4* buf = wb + (t & 1) * TWORDS;
        const uint2* A1 = Ar1 + t * 8;
        const uint2* A2 = Ar2 + t * 8;
        uint2 p0 = A1[tg], p2 = A1[tg + 4];
        uint2 q0 = A2[tg], q2 = A2[tg + 4];
        unsigned ahi[4] = {p0.x, q0.x, p2.x, q2.x};
        unsigned alo[4] = {p0.y, q0.y, p2.y, q2.y};
        const uint4* bp = buf + cbase * 4 + tg;
#pragma unroll
        for (int nt = 0; nt < 8; ++nt) {
            uint4 b = bp[(nt * 8 + gid) * 4];
            mma16(c[nt], ahi, b.x, b.y);
            mma16(c[nt], alo, b.x, b.y);
            mma16(c[nt], ahi, b.z, b.w);
        }
        if (t + 1 < ntiles) {
            wb[((t + 1) & 1) * TWORDS + tid] = w0;
            if (t + 2 < ntiles) w0 = Wp[(size_t)(t + 2) * TWORDS + tid];
        }
    }
}

__device__ __forceinline__ void zero_c(float c[8][4]) {
#pragma unroll
    for (int i = 0; i < 8; ++i)
#pragma unroll
        for (int j = 0; j < 4; ++j) c[i][j] = 0.f;
}

// ---------------- edge kernel smem layout (bytes) ----------------
#define EA_BYTES (ETILE * EP2 * 8)           // 167936
#define OFF_WB   EA_BYTES
#define OFF_XR   (OFF_WB + 2 * TWORDS * 16)  // +16384
#define OFF_RED  (OFF_XR + ETILE * 3 * 4)
#define OFF_CV   (OFF_RED + ETILE * 2 * 8)
#define OFF_DST  (OFF_CV + ETILE * 2 * 4)
#define OFF_SRC  (OFF_DST + ETILE * 4)
#define SMEM_E   (OFF_SRC + ETILE * 4)       // 189952

// ---------------------------------------------------------------------------
// Edge kernel: 128 edges per block, 512 threads, 1 CTA/SM.
//   pairs 0..63  : feats[src]  | pairs 64..127: feats[dst] (m after GEMM2)
//   pairs 128..143: edge_feats | pairs 144..151: rbf + pad
//   h1 overlay on pairs 0..63 after GEMM1.
// ---------------------------------------------------------------------------
__global__ __launch_bounds__(ETHREADS, 1)
void edge_kernel(const float* __restrict__ feats, const float* __restrict__ x,
                 const float* __restrict__ edge_feats,
                 const int* __restrict__ src, const int* __restrict__ dst,
                 const float* __restrict__ eb1, const float* __restrict__ eg1,
                 const float* __restrict__ ebn1, const float* __restrict__ eb2,
                 const float* __restrict__ cb1, const float* __restrict__ cW2, int E)
{
    extern __shared__ char smb[];
    uint2*  ea    = (uint2*)smb;
    uint4*  wb    = (uint4*)(smb + OFF_WB);
    float*  xr    = (float*)(smb + OFF_XR);
    float2* red   = (float2*)(smb + OFF_RED);
    float*  cvred = (float*)(smb + OFF_CV);
    int*    sdst  = (int*)(smb + OFF_DST);
    int*    ssrc  = (int*)(smb + OFF_SRC);

    const int tid = threadIdx.x;
    const int e0 = blockIdx.x * ETILE;

    if (tid < ETILE) {
        int e = e0 + tid;
        int s = 0, d = 0;
        if (e < E) { s = src[e]; d = dst[e]; }
        ssrc[tid] = s; sdst[tid] = d;
    }
    __syncthreads();

    // Gather features as packed bf16 hi/lo pairs (L2-resident table)
    for (int idx = tid; idx < ETILE * 128; idx += ETHREADS) {
        int row = idx >> 7, pk = idx & 127;
        const float* fp = (pk < 64)
            ? feats + (size_t)ssrc[row] * 128 + pk * 2
            : feats + (size_t)sdst[row] * 128 + (pk - 64) * 2;
        float2 v = *(const float2*)fp;
        unsigned h, l; split2(v, h, l);
        ea[row * EP2 + pk] = make_uint2(h, l);
    }
    for (int idx = tid; idx < ETILE * 16; idx += ETHREADS) {
        int row = idx >> 4, pp = idx & 15;
        int e = e0 + row;
        float2 v = make_float2(0.f, 0.f);
        if (e < E) v = *(const float2*)(edge_feats + (size_t)e * 32 + pp * 2);
        unsigned h, l; split2(v, h, l);
        ea[row * EP2 + 128 + pp] = make_uint2(h, l);
    }
    if (tid < ETILE) {
        int e = e0 + tid;
        float rx = 0.f, ry = 0.f, rz = 0.f;
        if (e < E) {
            int s = ssrc[tid], d = sdst[tid];
            rx = x[3 * s + 0] - x[3 * d + 0];
            ry = x[3 * s + 1] - x[3 * d + 1];
            rz = x[3 * s + 2] - x[3 * d + 2];
            float nrm = sqrtf(rx * rx + ry * ry + rz * rz) + 1.0f;
            float inv = 1.0f / nrm;
            rx *= inv; ry *= inv; rz *= inv;
        }
        xr[tid * 3 + 0] = rx; xr[tid * 3 + 1] = ry; xr[tid * 3 + 2] = rz;
        float d2 = rx * rx + ry * ry + rz * rz;
        float rb[16];
        float sig = 1.0f;
#pragma unroll
        for (int i = 0; i < 15; ++i) { rb[i] = expf(-d2 / sig); sig *= 1.5f; }
        rb[15] = 0.f;
#pragma unroll
        for (int p2 = 0; p2 < 8; ++p2) {
            unsigned h, l; split2(make_float2(rb[2 * p2], rb[2 * p2 + 1]), h, l);
            ea[tid * EP2 + 144 + p2] = make_uint2(h, l);
        }
    }
    // (gemm_pk's internal syncs order the gather writes before MMA reads)

    const int lane = tid & 31, warp = tid >> 5;
    const int gid = lane >> 2, tg = lane & 3;
    const int rbase = (warp & 7) * 16;      // 8 row-groups x 16 rows = 128
    const int cbase = (warp >> 3) * 64;     // 2 column halves
    const int half = warp >> 3;
    const int r1 = rbase + gid, r2 = r1 + 8;

    float c[8][4];

    // ---- GEMM1: e_in(304 padded) @ eW1 -> 128   (19 k16 tiles)
    zero_c(c);
    gemm_pk(ea, 0, g_eW1p, 19, wb, tid, r1, cbase, gid, tg, c);

    // ---- bias + lrelu + LayerNorm -> h1 packed into pairs 0..63
    {
        float s1 = 0.f, q1 = 0.f, s2 = 0.f, q2 = 0.f;
#pragma unroll
        for (int nt = 0; nt < 8; ++nt) {
            int col = cbase + nt * 8 + 2 * tg;
            float2 b = *(const float2*)(eb1 + col);
            float t00 = lrelu(c[nt][0] + b.x), t01 = lrelu(c[nt][1] + b.y);
            float t10 = lrelu(c[nt][2] + b.x), t11 = lrelu(c[nt][3] + b.y);
            c[nt][0] = t00; c[nt][1] = t01; c[nt][2] = t10; c[nt][3] = t11;
            s1 += t00 + t01; q1 += t00 * t00 + t01 * t01;
            s2 += t10 + t11; q2 += t10 * t10 + t11 * t11;
        }
#pragma unroll
        for (int off = 1; off <= 2; off <<= 1) {
            s1 += __shfl_xor_sync(0xffffffffu, s1, off);
            q1 += __shfl_xor_sync(0xffffffffu, q1, off);
            s2 += __shfl_xor_sync(0xffffffffu, s2, off);
            q2 += __shfl_xor_sync(0xffffffffu, q2, off);
        }
        if (tg == 0) {
            red[r1 * 2 + half] = make_float2(s1, q1);
            red[r2 * 2 + half] = make_float2(s2, q2);
        }
        __syncthreads();   // red visible; all GEMM1 reads done -> pair 0..63 overlay safe
        float2 u = red[r1 * 2 + 0], v = red[r1 * 2 + 1];
        float m1 = (u.x + v.x) * (1.f / 128.f);
        float inv1 = rsqrtf((u.y + v.y) * (1.f / 128.f) - m1 * m1 + 1e-5f);
        u = red[r2 * 2 + 0]; v = red[r2 * 2 + 1];
        float m2 = (u.x + v.x) * (1.f / 128.f);
        float inv2 = rsqrtf((u.y + v.y) * (1.f / 128.f) - m2 * m2 + 1e-5f);
#pragma unroll
        for (int nt = 0; nt < 8; ++nt) {
            int col = cbase + nt * 8 + 2 * tg;
            float2 g = *(const float2*)(eg1 + col);
            float2 bt = *(const float2*)(ebn1 + col);
            float h0 = (c[nt][0] - m1) * inv1 * g.x + bt.x;
            float h1v = (c[nt][1] - m1) * inv1 * g.y + bt.y;
            float h2 = (c[nt][2] - m2) * inv2 * g.x + bt.x;
            float h3 = (c[nt][3] - m2) * inv2 * g.y + bt.y;
            unsigned hh, ll;
            split2(make_float2(h0, h1v), hh, ll);
            ea[r1 * EP2 + (col >> 1)] = make_uint2(hh, ll);
            split2(make_float2(h2, h3), hh, ll);
            ea[r2 * EP2 + (col >> 1)] = make_uint2(hh, ll);
        }
    }

    // ---- GEMM2: h1 @ eW2 -> m (lrelu), packed into pairs 64..127
    zero_c(c);
    gemm_pk(ea, 0, g_eW2p, 8, wb, tid, r1, cbase, gid, tg, c);
    {
#pragma unroll
        for (int nt = 0; nt < 8; ++nt) {
            int col = cbase + nt * 8 + 2 * tg;
            float2 b = *(const float2*)(eb2 + col);
            float m0 = lrelu(c[nt][0] + b.x), m1v = lrelu(c[nt][1] + b.y);
            float m2v = lrelu(c[nt][2] + b.x), m3 = lrelu(c[nt][3] + b.y);
            unsigned hh, ll;
            split2(make_float2(m0, m1v), hh, ll);
            ea[r1 * EP2 + 64 + (col >> 1)] = make_uint2(hh, ll);
            split2(make_float2(m2v, m3), hh, ll);
            ea[r2 * EP2 + 64 + (col >> 1)] = make_uint2(hh, ll);
        }
    }

    // ---- GEMM3: t = lrelu(m @ cW1 + cb1); c_coef = t . cW2
    zero_c(c);
    gemm_pk(ea, 64, g_cW1p, 8, wb, tid, r1, cbase, gid, tg, c);
    {
        float p1 = 0.f, p2 = 0.f;
#pragma unroll
        for (int nt = 0; nt < 8; ++nt) {
            int col = cbase + nt * 8 + 2 * tg;
            float2 b = *(const float2*)(cb1 + col);
            float2 w = *(const float2*)(cW2 + col);
            p1 += lrelu(c[nt][0] + b.x) * w.x + lrelu(c[nt][1] + b.y) * w.y;
            p2 += lrelu(c[nt][2] + b.x) * w.x + lrelu(c[nt][3] + b.y) * w.y;
        }
#pragma unroll
        for (int off = 1; off <= 2; off <<= 1) {
            p1 += __shfl_xor_sync(0xffffffffu, p1, off);
            p2 += __shfl_xor_sync(0xffffffffu, p2, off);
        }
        if (tg == 0) {
            cvred[r1 * 2 + half] = p1;
            cvred[r2 * 2 + half] = p2;
        }
    }
    __syncthreads();

    // ---- Aggregation: m = hi+lo reconstructed from pairs 64..127
    for (int idx = tid; idx < ETILE * 32; idx += ETHREADS) {
        int row = idx >> 5, col4 = (idx & 31) * 4;
        int e = e0 + row;
        if (e < E) {
            uint2 u0 = ea[row * EP2 + 64 + (col4 >> 1)];
            uint2 u1 = ea[row * EP2 + 64 + (col4 >> 1) + 1];
            float4 v = make_float4(bf16_lo_f(u0.x) + bf16_lo_f(u0.y),
                                   bf16_hi_f(u0.x) + bf16_hi_f(u0.y),
                                   bf16_lo_f(u1.x) + bf16_lo_f(u1.y),
                                   bf16_hi_f(u1.x) + bf16_hi_f(u1.y));
            red_v4(g_aggr + (size_t)sdst[row] * 128 + col4, v);
        }
    }
    if (tid < ETILE) {
        int e = e0 + tid;
        if (e < E) {
            float cv = cvred[tid * 2] + cvred[tid * 2 + 1];
            int dn = sdst[tid];
            atomicAdd(&g_xsum[(size_t)dn * 3 + 0], xr[tid * 3 + 0] * cv);
            atomicAdd(&g_xsum[(size_t)dn * 3 + 1], xr[tid * 3 + 1] * cv);
            atomicAdd(&g_xsum[(size_t)dn * 3 + 2], xr[tid * 3 + 2] * cv);
            atomicAdd(&g_cnt[dn], 1.0f);
        }
    }
}

// ===========================================================================
// Node kernel (mma.sync bf16x3, fused uint4 weights) — unchanged from R12.
// ===========================================================================
__device__ __forceinline__ void gemm_mma(const float* __restrict__ As, int astride,
                                         const uint4* __restrict__ Wp, int ntiles,
                                         uint4* __restrict__ wb,
                                         int tid, int rbase, int cbase, int gid, int tg,
                                         float c[8][4])
{
    uint4 r0 = Wp[tid], r1 = Wp[tid + 256];
    const float* Ar1 = As + (size_t)(rbase + gid) * astride;
    const float* Ar2 = Ar1 + 8 * astride;
    __syncthreads();
    wb[tid] = r0; wb[tid + 256] = r1;
    if (ntiles > 1) { r0 = Wp[TWORDS + tid]; r1 = Wp[TWORDS + tid + 256]; }
#pragma unroll 1
    for (int t = 0; t < ntiles; ++t) {
        __syncthreads();
        const uint4* buf = wb + (t & 1) * TWORDS;
        int kA = t * 16 + tg * 2;
        float2 a00 = *(const float2*)(Ar1 + kA);
        float2 a01 = *(const float2*)(Ar1 + kA + 8);
        float2 a10 = *(const float2*)(Ar2 + kA);
        float2 a11 = *(const float2*)(Ar2 + kA + 8);
        unsigned ahi[4], alo[4];
        split2(a00, ahi[0], alo[0]);
        split2(a10, ahi[1], alo[1]);
        split2(a01, ahi[2], alo[2]);
        split2(a11, ahi[3], alo[3]);
        const uint4* bp = buf + cbase * 4 + tg;
#pragma unroll
        for (int nt = 0; nt < 8; ++nt) {
            uint4 b = bp[(nt * 8 + gid) * 4];
            mma16(c[nt], ahi, b.x, b.y);
            mma16(c[nt], alo, b.x, b.y);
            mma16(c[nt], ahi, b.z, b.w);
        }
        if (t + 1 < ntiles) {
            uint4* nbuf = wb + ((t + 1) & 1) * TWORDS;
            nbuf[tid] = r0; nbuf[tid + 256] = r1;
            if (t + 2 < ntiles) {
                r0 = Wp[(size_t)(t + 2) * TWORDS + tid];
                r1 = Wp[(size_t)(t + 2) * TWORDS + tid + 256];
            }
        }
    }
}

__global__ __launch_bounds__(256, 2)
void node_kernel(const float* __restrict__ feats, const float* __restrict__ orig,
                 const float* __restrict__ x,
                 const float* __restrict__ nng, const float* __restrict__ nnb,
                 const float* __restrict__ nb1, const float* __restrict__ ng1,
                 const float* __restrict__ nbn1, const float* __restrict__ nb2,
                 float* __restrict__ out, int N)
{
    extern __shared__ float sm[];
    float*  nin = sm;
    uint4*  wb  = (uint4*)(nin + TILE * ESTRIDE);
    float2* red = (float2*)(wb + 2 * TWORDS);
    float*  nh  = nin;

    const int tid = threadIdx.x;
    const int n0 = blockIdx.x * TILE;

    for (int idx = tid; idx < TILE * 128; idx += 256) {
        int r = idx >> 7, c = idx & 127;
        int n = n0 + r;
        nin[r * ESTRIDE + c]       = (n < N) ? feats[(size_t)n * 128 + c] : 0.f;
        nin[r * ESTRIDE + 128 + c] = (n < N) ? g_aggr[(size_t)n * 128 + c] : 0.f;
    }
    for (int idx = tid; idx < TILE * 64; idx += 256) {
        int r = idx >> 6, c = idx & 63;
        int n = n0 + r;
        nin[r * ESTRIDE + 256 + c] = (n < N) ? orig[(size_t)n * 64 + c] : 0.f;
    }
    __syncthreads();

    const int lane = tid & 31, warp = tid >> 5;

    {
        const int rg = lane >> 4;
        const int r0s = warp * 8 + rg * 4;
        const int cbs = (lane & 15) * 8;
        float4 g0 = *(const float4*)(nng + cbs), g1v = *(const float4*)(nng + cbs + 4);
        float gg[8] = {g0.x, g0.y, g0.z, g0.w, g1v.x, g1v.y, g1v.z, g1v.w};
        float4 q0 = *(const float4*)(nnb + cbs), q1 = *(const float4*)(nnb + cbs + 4);
        float qq[8] = {q0.x, q0.y, q0.z, q0.w, q1.x, q1.y, q1.z, q1.w};
#pragma unroll
        for (int rr = 0; rr < 4; ++rr) {
            float* rp = nin + (r0s + rr) * ESTRIDE + cbs;
            float v[8]; float s = 0.f, q = 0.f;
#pragma unroll
            for (int cc = 0; cc < 8; ++cc) { v[cc] = rp[cc]; s += v[cc]; q += v[cc] * v[cc]; }
#pragma unroll
            for (int off = 8; off >= 1; off >>= 1) {
                s += __shfl_xor_sync(0xffffffffu, s, off);
                q += __shfl_xor_sync(0xffffffffu, q, off);
            }
            float mean = s * (1.f / 128.f);
            float var = q * (1.f / 128.f) - mean * mean;
            float inv = rsqrtf(var + 1e-5f);
#pragma unroll
            for (int cc = 0; cc < 8; ++cc)
                rp[cc] = (v[cc] - mean) * inv * gg[cc] + qq[cc];
        }
    }

    const int gid = lane >> 2, tg = lane & 3;
    const int rbase = (warp & 3) * 16;
    const int cbase = (warp >> 2) * 64;
    const int half = warp >> 2;
    const int r1 = rbase + gid, r2 = r1 + 8;

    float c[8][4];
    zero_c(c);
    gemm_mma(nin, ESTRIDE, g_nW1p, 20, wb, tid, rbase, cbase, gid, tg, c);
    {
        float s1 = 0.f, q1 = 0.f, s2 = 0.f, q2 = 0.f;
#pragma unroll
        for (int nt = 0; nt < 8; ++nt) {
            int col = cbase + nt * 8 + 2 * tg;
            float2 b = *(const float2*)(nb1 + col);
            float t00 = lrelu(c[nt][0] + b.x), t01 = lrelu(c[nt][1] + b.y);
            float t10 = lrelu(c[nt][2] + b.x), t11 = lrelu(c[nt][3] + b.y);
            c[nt][0] = t00; c[nt][1] = t01; c[nt][2] = t10; c[nt][3] = t11;
            s1 += t00 + t01; q1 += t00 * t00 + t01 * t01;
            s2 += t10 + t11; q2 += t10 * t10 + t11 * t11;
        }
#pragma unroll
        for (int off = 1; off <= 2; off <<= 1) {
            s1 += __shfl_xor_sync(0xffffffffu, s1, off);
            q1 += __shfl_xor_sync(0xffffffffu, q1, off);
            s2 += __shfl_xor_sync(0xffffffffu, s2, off);
            q2 += __shfl_xor_sync(0xffffffffu, q2, off);
        }
        if (tg == 0) {
            red[r1 * 2 + half] = make_float2(s1, q1);
            red[r2 * 2 + half] = make_float2(s2, q2);
        }
        __syncthreads();
        float2 u = red[r1 * 2 + 0], v = red[r1 * 2 + 1];
        float m1 = (u.x + v.x) * (1.f / 128.f);
        float inv1 = rsqrtf((u.y + v.y) * (1.f / 128.f) - m1 * m1 + 1e-5f);
        u = red[r2 * 2 + 0]; v = red[r2 * 2 + 1];
        float m2 = (u.x + v.x) * (1.f / 128.f);
        float inv2 = rsqrtf((u.y + v.y) * (1.f / 128.f) - m2 * m2 + 1e-5f);
#pragma unroll
        for (int nt = 0; nt < 8; ++nt) {
            int col = cbase + nt * 8 + 2 * tg;
            float2 g = *(const float2*)(ng1 + col);
            float2 bt = *(const float2*)(nbn1 + col);
            *(float2*)(nh + r1 * HSTRIDE + col) =
                make_float2((c[nt][0] - m1) * inv1 * g.x + bt.x,
                            (c[nt][1] - m1) * inv1 * g.y + bt.y);
            *(float2*)(nh + r2 * HSTRIDE + col) =
                make_float2((c[nt][2] - m2) * inv2 * g.x + bt.x,
                            (c[nt][3] - m2) * inv2 * g.y + bt.y);
        }
    }

    zero_c(c);
    gemm_mma(nh, HSTRIDE, g_nW2p, 8, wb, tid, rbase, cbase, gid, tg, c);
    {
        int n1 = n0 + r1, n2 = n0 + r2;
#pragma unroll
        for (int nt = 0; nt < 8; ++nt) {
            int col = cbase + nt * 8 + 2 * tg;
            float2 b = *(const float2*)(nb2 + col);
            if (n1 < N) {
                float2 f = *(const float2*)(feats + (size_t)n1 * 128 + col);
                *(float2*)(out + (size_t)n1 * 128 + col) =
                    make_float2(0.75f * (c[nt][0] + b.x) + 0.25f * f.x,
                                0.75f * (c[nt][1] + b.y) + 0.25f * f.y);
            }
            if (n2 < N) {
                float2 f = *(const float2*)(feats + (size_t)n2 * 128 + col);
                *(float2*)(out + (size_t)n2 * 128 + col) =
                    make_float2(0.75f * (c[nt][2] + b.x) + 0.25f * f.x,
                                0.75f * (c[nt][3] + b.y) + 0.25f * f.y);
            }
        }
    }
    if (tid < TILE) {
        int n = n0 + tid;
        if (n < N) {
            float cnt = g_cnt[n];
            if (cnt < 1.f) cnt = 1.f;
            float inv = 1.f / cnt;
            size_t base = (size_t)N * 128 + (size_t)n * 3;
            out[base + 0] = x[(size_t)n * 3 + 0] + g_xsum[(size_t)n * 3 + 0] * inv;
            out[base + 1] = x[(size_t)n * 3 + 1] + g_xsum[(size_t)n * 3 + 1] * inv;
            out[base + 2] = x[(size_t)n * 3 + 2] + g_xsum[(size_t)n * 3 + 2] * inv;
        }
    }
}

extern "C" void kernel_launch(void* const* d_in, const int* in_sizes, int n_in,
                              void* d_out, int out_size)
{
    const float* feats      = (const float*)d_in[0];
    const float* orig       = (const float*)d_in[1];
    const float* x          = (const float*)d_in[2];
    /* d_in[3] = x_orig, unused (X_CONN_INIT = 0) */
    const float* edge_feats = (const float*)d_in[4];
    const int*   src        = (const int*)d_in[5];
    const int*   dst        = (const int*)d_in[6];
    const float* eW1  = (const float*)d_in[7];
    const float* eb1  = (const float*)d_in[8];
    const float* eg1  = (const float*)d_in[9];
    const float* ebn1 = (const float*)d_in[10];
    const float* eW2  = (const float*)d_in[11];
    const float* eb2  = (const float*)d_in[12];
    const float* nng  = (const float*)d_in[13];
    const float* nnb  = (const float*)d_in[14];
    const float* nW1  = (const float*)d_in[15];
    const float* nb1  = (const float*)d_in[16];
    const float* ng1  = (const float*)d_in[17];
    const float* nbn1 = (const float*)d_in[18];
    const float* nW2  = (const float*)d_in[19];
    const float* nb2  = (const float*)d_in[20];
    const float* cW1  = (const float*)d_in[21];
    const float* cb1  = (const float*)d_in[22];
    const float* cW2  = (const float*)d_in[23];

    const int N = in_sizes[0] / HID;
    const int E = in_sizes[5];

    void *aggr_p, *xs_p, *cnt_p;
    cudaGetSymbolAddress(&aggr_p, g_aggr);
    cudaGetSymbolAddress(&xs_p, g_xsum);
    cudaGetSymbolAddress(&cnt_p, g_cnt);
    cudaMemsetAsync(aggr_p, 0, (size_t)N * OUT * sizeof(float), 0);
    cudaMemsetAsync(xs_p, 0, (size_t)N * 3 * sizeof(float), 0);
    cudaMemsetAsync(cnt_p, 0, (size_t)N * sizeof(float), 0);

    prepack_kernel<<<126, 256>>>(eW1, eW2, cW1, nW1, nW2);

    const int SMEM_N = (TILE * ESTRIDE + TILE * 2 * 2) * 4 + 2 * TWORDS * 16;
    cudaFuncSetAttribute(edge_kernel, cudaFuncAttributeMaxDynamicSharedMemorySize, SMEM_E);
    cudaFuncSetAttribute(node_kernel, cudaFuncAttributeMaxDynamicSharedMemorySize, SMEM_N);

    int eblocks = (E + ETILE - 1) / ETILE;
    edge_kernel<<<eblocks, ETHREADS, SMEM_E>>>(feats, x, edge_feats, src, dst,
                                               eb1, eg1, ebn1, eb2, cb1, cW2, E);

    int nblocks = (N + TILE - 1) / TILE;
    node_kernel<<<nblocks, 256, SMEM_N>>>(feats, orig, x, nng, nnb,
                                          nb1, ng1, nbn1, nb2,
                                          (float*)d_out, N);
}

// round 17
// speedup vs baseline: 1.1771x; 1.1771x over previous
#include <cuda_runtime.h>
#include <cuda_bf16.h>
#include <math.h>

#define HID 128
#define OUT 128
#define NMAX 50000
#define TILE 64
#define TWORDS 512    // uint4 per weight tile
#define EP2 164       // packed-A stride in uint2 (row = 1312 B)

// ---------------- device scratch (no allocations anywhere) ----------------
__device__ float g_aggr[(size_t)NMAX * OUT];
__device__ float g_xsum[(size_t)NMAX * 3];
__device__ float g_cnt[NMAX];

// Fused-fragment weights: per tile/col/tg -> uint4{bh0,bh1,bl0,bl1}
__device__ uint4 g_eW1p[19 * TWORDS];
__device__ uint4 g_eW2p[8 * TWORDS];
__device__ uint4 g_cW1p[8 * TWORDS];
__device__ uint4 g_nW1p[20 * TWORDS];
__device__ uint4 g_nW2p[8 * TWORDS];

__device__ __forceinline__ float lrelu(float v) { return v > 0.f ? v : 0.01f * v; }

// ---------------- bf16 split helpers ----------------
__device__ __forceinline__ unsigned bf16x2_pack(float a, float b) {
    unsigned r;
    asm("cvt.rn.bf16x2.f32 %0, %1, %2;" : "=r"(r) : "f"(b), "f"(a));
    return r;
}
__device__ __forceinline__ float bf16_lo_f(unsigned p) { return __uint_as_float(p << 16); }
__device__ __forceinline__ float bf16_hi_f(unsigned p) { return __uint_as_float(p & 0xffff0000u); }
__device__ __forceinline__ void split2(float2 a, unsigned& hi, unsigned& lo) {
    hi = bf16x2_pack(a.x, a.y);
    lo = bf16x2_pack(a.x - bf16_lo_f(hi), a.y - bf16_hi_f(hi));
}

// m16n8k16 bf16 MMA, C += A*B
__device__ __forceinline__ void mma16(float c[4], const unsigned a[4], unsigned b0, unsigned b1) {
    asm("mma.sync.aligned.m16n8k16.row.col.f32.bf16.bf16.f32 "
        "{%0,%1,%2,%3}, {%4,%5,%6,%7}, {%8,%9}, {%0,%1,%2,%3};"
        : "+f"(c[0]), "+f"(c[1]), "+f"(c[2]), "+f"(c[3])
        : "r"(a[0]), "r"(a[1]), "r"(a[2]), "r"(a[3]), "r"(b0), "r"(b1));
}

__device__ __forceinline__ void red_v4(float* addr, float4 v) {
    asm volatile("red.global.add.v4.f32 [%0], {%1,%2,%3,%4};"
                 :: "l"(addr), "f"(v.x), "f"(v.y), "f"(v.z), "f"(v.w) : "memory");
}

// ---------------- prepack kernel: fp32 weights -> fused uint4 fragments -----
__device__ __forceinline__ float wval(const float* W, int k, int col, int krows, bool remap) {
    if (k >= krows) return 0.f;
    int kr = (remap && k >= 256) ? k + 128 : k;
    return W[(size_t)kr * 128 + col];
}

__global__ void prepack_kernel(const float* __restrict__ eW1, const float* __restrict__ eW2,
                               const float* __restrict__ cW1, const float* __restrict__ nW1,
                               const float* __restrict__ nW2)
{
    int idx = blockIdx.x * 256 + threadIdx.x;
    if (idx >= 63 * TWORDS) return;
    int within = idx & (TWORDS - 1);
    int gt = idx >> 9;
    int col = within >> 2, tg = within & 3;

    const float* W; uint4* Out; int lt, krows; bool remap = false;
    if (gt < 19)      { W = eW1; Out = g_eW1p; lt = gt;      krows = 303; }
    else if (gt < 27) { W = eW2; Out = g_eW2p; lt = gt - 19; krows = 128; }
    else if (gt < 35) { W = cW1; Out = g_cW1p; lt = gt - 27; krows = 128; }
    else if (gt < 55) { W = nW1; Out = g_nW1p; lt = gt - 35; krows = 320; remap = true; }
    else              { W = nW2; Out = g_nW2p; lt = gt - 55; krows = 128; }

    int k0 = (lt * 8 + tg) * 2;
    int k2 = (lt * 8 + tg + 4) * 2;
    float a0 = wval(W, k0, col, krows, remap), a1 = wval(W, k0 + 1, col, krows, remap);
    float a2 = wval(W, k2, col, krows, remap), a3 = wval(W, k2 + 1, col, krows, remap);

    unsigned h0 = bf16x2_pack(a0, a1);
    unsigned h1 = bf16x2_pack(a2, a3);
    unsigned l0 = bf16x2_pack(a0 - bf16_lo_f(h0), a1 - bf16_hi_f(h0));
    unsigned l1 = bf16x2_pack(a2 - bf16_lo_f(h1), a3 - bf16_hi_f(h1));
    Out[lt * TWORDS + within] = make_uint4(h0, h1, l0, l1);
}

// ---------------- shared GEMM (256 threads): packed-A + fused uint4 B -------
__device__ __forceinline__ void gemm_pk(const uint2* __restrict__ ea, int abase,
                                        const uint4* __restrict__ Wp, int ntiles,
                                        uint4* __restrict__ wb,
                                        int tid, int r1, int cbase, int gid, int tg,
                                        float c[8][4])
{
    uint4 w0 = Wp[tid], w1 = Wp[tid + 256];
    const uint2* Ar1 = ea + (size_t)r1 * EP2 + abase;
    const uint2* Ar2 = Ar1 + 8 * EP2;
    __syncthreads();                      // prior consumers of wb / producers of ea done
    wb[tid] = w0; wb[tid + 256] = w1;
    if (ntiles > 1) { w0 = Wp[TWORDS + tid]; w1 = Wp[TWORDS + tid + 256]; }
#pragma unroll 1
    for (int t = 0; t < ntiles; ++t) {
        __syncthreads();                  // tile t visible; all warps done with tile t-1
        const uint4* buf = wb + (t & 1) * TWORDS;
        const uint2* A1 = Ar1 + t * 8;
        const uint2* A2 = Ar2 + t * 8;
        uint2 p0 = A1[tg], p2 = A1[tg + 4];
        uint2 q0 = A2[tg], q2 = A2[tg + 4];
        unsigned ahi[4] = {p0.x, q0.x, p2.x, q2.x};
        unsigned alo[4] = {p0.y, q0.y, p2.y, q2.y};
        const uint4* bp = buf + cbase * 4 + tg;
#pragma unroll
        for (int nt = 0; nt < 8; ++nt) {
            uint4 b = bp[(nt * 8 + gid) * 4];
            mma16(c[nt], ahi, b.x, b.y);
            mma16(c[nt], alo, b.x, b.y);
            mma16(c[nt], ahi, b.z, b.w);
        }
        if (t + 1 < ntiles) {
            uint4* nbuf = wb + ((t + 1) & 1) * TWORDS;
            nbuf[tid] = w0; nbuf[tid + 256] = w1;
            if (t + 2 < ntiles) {
                w0 = Wp[(size_t)(t + 2) * TWORDS + tid];
                w1 = Wp[(size_t)(t + 2) * TWORDS + tid + 256];
            }
        }
    }
}

__device__ __forceinline__ void zero_c(float c[8][4]) {
#pragma unroll
    for (int i = 0; i < 8; ++i)
#pragma unroll
        for (int j = 0; j < 4; ++j) c[i][j] = 0.f;
}

// ---------------- edge kernel smem layout (bytes) — R12 winner ----------------
#define EA_BYTES (TILE * EP2 * 8)            // 83968
#define OFF_WB   EA_BYTES
#define OFF_XR   (OFF_WB + 2 * TWORDS * 16)  // +16384
#define OFF_RED  (OFF_XR + TILE * 3 * 4)
#define OFF_CV   (OFF_RED + TILE * 2 * 8)
#define OFF_DST  (OFF_CV + TILE * 2 * 4)
#define OFF_SRC  (OFF_DST + TILE * 4)
#define SMEM_E   (OFF_SRC + TILE * 4)        // 103168

// ---------------------------------------------------------------------------
// Edge kernel: 64 edges per block, 256 threads, 2 CTAs/SM (R12 configuration).
// ---------------------------------------------------------------------------
__global__ __launch_bounds__(256, 2)
void edge_kernel(const float* __restrict__ feats, const float* __restrict__ x,
                 const float* __restrict__ edge_feats,
                 const int* __restrict__ src, const int* __restrict__ dst,
                 const float* __restrict__ eb1, const float* __restrict__ eg1,
                 const float* __restrict__ ebn1, const float* __restrict__ eb2,
                 const float* __restrict__ cb1, const float* __restrict__ cW2, int E)
{
    extern __shared__ char smb[];
    uint2*  ea    = (uint2*)smb;
    uint4*  wb    = (uint4*)(smb + OFF_WB);
    float*  xr    = (float*)(smb + OFF_XR);
    float2* red   = (float2*)(smb + OFF_RED);
    float*  cvred = (float*)(smb + OFF_CV);
    int*    sdst  = (int*)(smb + OFF_DST);
    int*    ssrc  = (int*)(smb + OFF_SRC);

    const int tid = threadIdx.x;
    const int e0 = blockIdx.x * TILE;

    if (tid < TILE) {
        int e = e0 + tid;
        int s = 0, d = 0;
        if (e < E) { s = src[e]; d = dst[e]; }
        ssrc[tid] = s; sdst[tid] = d;
    }
    __syncthreads();

    for (int idx = tid; idx < TILE * 128; idx += 256) {
        int row = idx >> 7, pk = idx & 127;
        const float* fp = (pk < 64)
            ? feats + (size_t)ssrc[row] * 128 + pk * 2
            : feats + (size_t)sdst[row] * 128 + (pk - 64) * 2;
        float2 v = *(const float2*)fp;
        unsigned h, l; split2(v, h, l);
        ea[row * EP2 + pk] = make_uint2(h, l);
    }
    for (int idx = tid; idx < TILE * 16; idx += 256) {
        int row = idx >> 4, pp = idx & 15;
        int e = e0 + row;
        float2 v = make_float2(0.f, 0.f);
        if (e < E) v = *(const float2*)(edge_feats + (size_t)e * 32 + pp * 2);
        unsigned h, l; split2(v, h, l);
        ea[row * EP2 + 128 + pp] = make_uint2(h, l);
    }
    if (tid < TILE) {
        int e = e0 + tid;
        float rx = 0.f, ry = 0.f, rz = 0.f;
        if (e < E) {
            int s = ssrc[tid], d = sdst[tid];
            rx = x[3 * s + 0] - x[3 * d + 0];
            ry = x[3 * s + 1] - x[3 * d + 1];
            rz = x[3 * s + 2] - x[3 * d + 2];
            float nrm = sqrtf(rx * rx + ry * ry + rz * rz) + 1.0f;
            float inv = 1.0f / nrm;
            rx *= inv; ry *= inv; rz *= inv;
        }
        xr[tid * 3 + 0] = rx; xr[tid * 3 + 1] = ry; xr[tid * 3 + 2] = rz;
        float d2 = rx * rx + ry * ry + rz * rz;
        float rb[16];
        float sig = 1.0f;
#pragma unroll
        for (int i = 0; i < 15; ++i) { rb[i] = expf(-d2 / sig); sig *= 1.5f; }
        rb[15] = 0.f;
#pragma unroll
        for (int p2 = 0; p2 < 8; ++p2) {
            unsigned h, l; split2(make_float2(rb[2 * p2], rb[2 * p2 + 1]), h, l);
            ea[tid * EP2 + 144 + p2] = make_uint2(h, l);
        }
    }

    const int lane = tid & 31, warp = tid >> 5;
    const int gid = lane >> 2, tg = lane & 3;
    const int rbase = (warp & 3) * 16;
    const int cbase = (warp >> 2) * 64;
    const int half = warp >> 2;
    const int r1 = rbase + gid, r2 = r1 + 8;

    float c[8][4];

    // ---- GEMM1
    zero_c(c);
    gemm_pk(ea, 0, g_eW1p, 19, wb, tid, r1, cbase, gid, tg, c);

    // ---- bias + lrelu + LayerNorm -> h1 packed into pairs 0..63
    {
        float s1 = 0.f, q1 = 0.f, s2 = 0.f, q2 = 0.f;
#pragma unroll
        for (int nt = 0; nt < 8; ++nt) {
            int col = cbase + nt * 8 + 2 * tg;
            float2 b = *(const float2*)(eb1 + col);
            float t00 = lrelu(c[nt][0] + b.x), t01 = lrelu(c[nt][1] + b.y);
            float t10 = lrelu(c[nt][2] + b.x), t11 = lrelu(c[nt][3] + b.y);
            c[nt][0] = t00; c[nt][1] = t01; c[nt][2] = t10; c[nt][3] = t11;
            s1 += t00 + t01; q1 += t00 * t00 + t01 * t01;
            s2 += t10 + t11; q2 += t10 * t10 + t11 * t11;
        }
#pragma unroll
        for (int off = 1; off <= 2; off <<= 1) {
            s1 += __shfl_xor_sync(0xffffffffu, s1, off);
            q1 += __shfl_xor_sync(0xffffffffu, q1, off);
            s2 += __shfl_xor_sync(0xffffffffu, s2, off);
            q2 += __shfl_xor_sync(0xffffffffu, q2, off);
        }
        if (tg == 0) {
            red[r1 * 2 + half] = make_float2(s1, q1);
            red[r2 * 2 + half] = make_float2(s2, q2);
        }
        __syncthreads();
        float2 u = red[r1 * 2 + 0], v = red[r1 * 2 + 1];
        float m1 = (u.x + v.x) * (1.f / 128.f);
        float inv1 = rsqrtf((u.y + v.y) * (1.f / 128.f) - m1 * m1 + 1e-5f);
        u = red[r2 * 2 + 0]; v = red[r2 * 2 + 1];
        float m2 = (u.x + v.x) * (1.f / 128.f);
        float inv2 = rsqrtf((u.y + v.y) * (1.f / 128.f) - m2 * m2 + 1e-5f);
#pragma unroll
        for (int nt = 0; nt < 8; ++nt) {
            int col = cbase + nt * 8 + 2 * tg;
            float2 g = *(const float2*)(eg1 + col);
            float2 bt = *(const float2*)(ebn1 + col);
            float h0 = (c[nt][0] - m1) * inv1 * g.x + bt.x;
            float h1v = (c[nt][1] - m1) * inv1 * g.y + bt.y;
            float h2 = (c[nt][2] - m2) * inv2 * g.x + bt.x;
            float h3 = (c[nt][3] - m2) * inv2 * g.y + bt.y;
            unsigned hh, ll;
            split2(make_float2(h0, h1v), hh, ll);
            ea[r1 * EP2 + (col >> 1)] = make_uint2(hh, ll);
            split2(make_float2(h2, h3), hh, ll);
            ea[r2 * EP2 + (col >> 1)] = make_uint2(hh, ll);
        }
    }

    // ---- GEMM2 -> m packed into pairs 64..127
    zero_c(c);
    gemm_pk(ea, 0, g_eW2p, 8, wb, tid, r1, cbase, gid, tg, c);
    {
#pragma unroll
        for (int nt = 0; nt < 8; ++nt) {
            int col = cbase + nt * 8 + 2 * tg;
            float2 b = *(const float2*)(eb2 + col);
            float m0 = lrelu(c[nt][0] + b.x), m1v = lrelu(c[nt][1] + b.y);
            float m2v = lrelu(c[nt][2] + b.x), m3 = lrelu(c[nt][3] + b.y);
            unsigned hh, ll;
            split2(make_float2(m0, m1v), hh, ll);
            ea[r1 * EP2 + 64 + (col >> 1)] = make_uint2(hh, ll);
            split2(make_float2(m2v, m3), hh, ll);
            ea[r2 * EP2 + 64 + (col >> 1)] = make_uint2(hh, ll);
        }
    }

    // ---- GEMM3
    zero_c(c);
    gemm_pk(ea, 64, g_cW1p, 8, wb, tid, r1, cbase, gid, tg, c);
    {
        float p1 = 0.f, p2 = 0.f;
#pragma unroll
        for (int nt = 0; nt < 8; ++nt) {
            int col = cbase + nt * 8 + 2 * tg;
            float2 b = *(const float2*)(cb1 + col);
            float2 w = *(const float2*)(cW2 + col);
            p1 += lrelu(c[nt][0] + b.x) * w.x + lrelu(c[nt][1] + b.y) * w.y;
            p2 += lrelu(c[nt][2] + b.x) * w.x + lrelu(c[nt][3] + b.y) * w.y;
        }
#pragma unroll
        for (int off = 1; off <= 2; off <<= 1) {
            p1 += __shfl_xor_sync(0xffffffffu, p1, off);
            p2 += __shfl_xor_sync(0xffffffffu, p2, off);
        }
        if (tg == 0) {
            cvred[r1 * 2 + half] = p1;
            cvred[r2 * 2 + half] = p2;
        }
    }
    __syncthreads();

    // ---- Aggregation
    for (int idx = tid; idx < TILE * 32; idx += 256) {
        int row = idx >> 5, col4 = (idx & 31) * 4;
        int e = e0 + row;
        if (e < E) {
            uint2 u0 = ea[row * EP2 + 64 + (col4 >> 1)];
            uint2 u1 = ea[row * EP2 + 64 + (col4 >> 1) + 1];
            float4 v = make_float4(bf16_lo_f(u0.x) + bf16_lo_f(u0.y),
                                   bf16_hi_f(u0.x) + bf16_hi_f(u0.y),
                                   bf16_lo_f(u1.x) + bf16_lo_f(u1.y),
                                   bf16_hi_f(u1.x) + bf16_hi_f(u1.y));
            red_v4(g_aggr + (size_t)sdst[row] * 128 + col4, v);
        }
    }
    if (tid < TILE) {
        int e = e0 + tid;
        if (e < E) {
            float cv = cvred[tid * 2] + cvred[tid * 2 + 1];
            int dn = sdst[tid];
            atomicAdd(&g_xsum[(size_t)dn * 3 + 0], xr[tid * 3 + 0] * cv);
            atomicAdd(&g_xsum[(size_t)dn * 3 + 1], xr[tid * 3 + 1] * cv);
            atomicAdd(&g_xsum[(size_t)dn * 3 + 2], xr[tid * 3 + 2] * cv);
            atomicAdd(&g_cnt[dn], 1.0f);
        }
    }
}

// ---------------- node kernel smem layout (bytes) ----------------
#define N_OFF_WB   (TILE * EP2 * 8)             // 83968
#define N_OFF_RED  (N_OFF_WB + 2 * TWORDS * 16)
#define SMEM_N     (N_OFF_RED + TILE * 2 * 8)   // 101376

// ---------------------------------------------------------------------------
// Node kernel: 64 nodes per block, 2 CTAs/SM, direct gmem->packed gather
// (no fp32 staging, no overlay aliasing).
//   pairs 0..63  : LN(feats)  (register LN, packed on store)
//   pairs 64..127: aggr       | pairs 128..159: orig
//   nh overlay on pairs 0..63 after GEMM1.
// ---------------------------------------------------------------------------
__global__ __launch_bounds__(256, 2)
void node_kernel(const float* __restrict__ feats, const float* __restrict__ orig,
                 const float* __restrict__ x,
                 const float* __restrict__ nng, const float* __restrict__ nnb,
                 const float* __restrict__ nb1, const float* __restrict__ ng1,
                 const float* __restrict__ nbn1, const float* __restrict__ nb2,
                 float* __restrict__ out, int N)
{
    extern __shared__ char smb[];
    uint2*  ea  = (uint2*)smb;
    uint4*  wb  = (uint4*)(smb + N_OFF_WB);
    float2* red = (float2*)(smb + N_OFF_RED);

    const int tid = threadIdx.x;
    const int n0 = blockIdx.x * TILE;
    const int lane = tid & 31, warp = tid >> 5;

    // aggr -> pairs 64..127 (packed directly)
    for (int idx = tid; idx < TILE * 64; idx += 256) {
        int row = idx >> 6, p = idx & 63;
        int n = n0 + row;
        float2 v = (n < N) ? *(const float2*)(g_aggr + (size_t)n * 128 + 2 * p)
                           : make_float2(0.f, 0.f);
        unsigned h, l; split2(v, h, l);
        ea[row * EP2 + 64 + p] = make_uint2(h, l);
    }
    // orig -> pairs 128..159
    for (int idx = tid; idx < TILE * 32; idx += 256) {
        int row = idx >> 5, p = idx & 31;
        int n = n0 + row;
        float2 v = (n < N) ? *(const float2*)(orig + (size_t)n * 64 + 2 * p)
                           : make_float2(0.f, 0.f);
        unsigned h, l; split2(v, h, l);
        ea[row * EP2 + 128 + p] = make_uint2(h, l);
    }
    // LN(feats) in registers -> pairs 0..63
    {
        const int rg = lane >> 4;
        const int r0s = warp * 8 + rg * 4;
        const int cbs = (lane & 15) * 8;
        float4 g0 = *(const float4*)(nng + cbs), g1v = *(const float4*)(nng + cbs + 4);
        float gg[8] = {g0.x, g0.y, g0.z, g0.w, g1v.x, g1v.y, g1v.z, g1v.w};
        float4 q0 = *(const float4*)(nnb + cbs), q1 = *(const float4*)(nnb + cbs + 4);
        float qq[8] = {q0.x, q0.y, q0.z, q0.w, q1.x, q1.y, q1.z, q1.w};
#pragma unroll
        for (int rr = 0; rr < 4; ++rr) {
            int row = r0s + rr;
            int n = n0 + row;
            float v[8];
            if (n < N) {
                float4 a = *(const float4*)(feats + (size_t)n * 128 + cbs);
                float4 b = *(const float4*)(feats + (size_t)n * 128 + cbs + 4);
                v[0] = a.x; v[1] = a.y; v[2] = a.z; v[3] = a.w;
                v[4] = b.x; v[5] = b.y; v[6] = b.z; v[7] = b.w;
            } else {
#pragma unroll
                for (int cc = 0; cc < 8; ++cc) v[cc] = 0.f;
            }
            float s = 0.f, q = 0.f;
#pragma unroll
            for (int cc = 0; cc < 8; ++cc) { s += v[cc]; q += v[cc] * v[cc]; }
#pragma unroll
            for (int off = 8; off >= 1; off >>= 1) {
                s += __shfl_xor_sync(0xffffffffu, s, off);
                q += __shfl_xor_sync(0xffffffffu, q, off);
            }
            float mean = s * (1.f / 128.f);
            float var = q * (1.f / 128.f) - mean * mean;
            float inv = rsqrtf(var + 1e-5f);
#pragma unroll
            for (int j = 0; j < 4; ++j) {
                float e0v = (v[2 * j] - mean) * inv * gg[2 * j] + qq[2 * j];
                float e1v = (v[2 * j + 1] - mean) * inv * gg[2 * j + 1] + qq[2 * j + 1];
                unsigned h, l; split2(make_float2(e0v, e1v), h, l);
                ea[row * EP2 + (cbs >> 1) + j] = make_uint2(h, l);
            }
        }
    }
    // (gemm_pk's first __syncthreads orders all gather writes before MMA reads)

    const int gid = lane >> 2, tg = lane & 3;
    const int rbase = (warp & 3) * 16;
    const int cbase = (warp >> 2) * 64;
    const int half = warp >> 2;
    const int r1 = rbase + gid, r2 = r1 + 8;

    float c[8][4];

    // GEMM1: packed 320-dim input @ nW1 (remapped) -> 128   (20 tiles)
    zero_c(c);
    gemm_pk(ea, 0, g_nW1p, 20, wb, tid, r1, cbase, gid, tg, c);

    // bias + lrelu + LN -> nh packed into pairs 0..63
    {
        float s1 = 0.f, q1 = 0.f, s2 = 0.f, q2 = 0.f;
#pragma unroll
        for (int nt = 0; nt < 8; ++nt) {
            int col = cbase + nt * 8 + 2 * tg;
            float2 b = *(const float2*)(nb1 + col);
            float t00 = lrelu(c[nt][0] + b.x), t01 = lrelu(c[nt][1] + b.y);
            float t10 = lrelu(c[nt][2] + b.x), t11 = lrelu(c[nt][3] + b.y);
            c[nt][0] = t00; c[nt][1] = t01; c[nt][2] = t10; c[nt][3] = t11;
            s1 += t00 + t01; q1 += t00 * t00 + t01 * t01;
            s2 += t10 + t11; q2 += t10 * t10 + t11 * t11;
        }
#pragma unroll
        for (int off = 1; off <= 2; off <<= 1) {
            s1 += __shfl_xor_sync(0xffffffffu, s1, off);
            q1 += __shfl_xor_sync(0xffffffffu, q1, off);
            s2 += __shfl_xor_sync(0xffffffffu, s2, off);
            q2 += __shfl_xor_sync(0xffffffffu, q2, off);
        }
        if (tg == 0) {
            red[r1 * 2 + half] = make_float2(s1, q1);
            red[r2 * 2 + half] = make_float2(s2, q2);
        }
        __syncthreads();   // red visible; all GEMM1 reads done -> overlay safe
        float2 u = red[r1 * 2 + 0], v = red[r1 * 2 + 1];
        float m1 = (u.x + v.x) * (1.f / 128.f);
        float inv1 = rsqrtf((u.y + v.y) * (1.f / 128.f) - m1 * m1 + 1e-5f);
        u = red[r2 * 2 + 0]; v = red[r2 * 2 + 1];
        float m2 = (u.x + v.x) * (1.f / 128.f);
        float inv2 = rsqrtf((u.y + v.y) * (1.f / 128.f) - m2 * m2 + 1e-5f);
#pragma unroll
        for (int nt = 0; nt < 8; ++nt) {
            int col = cbase + nt * 8 + 2 * tg;
            float2 g = *(const float2*)(ng1 + col);
            float2 bt = *(const float2*)(nbn1 + col);
            float h0 = (c[nt][0] - m1) * inv1 * g.x + bt.x;
            float h1v = (c[nt][1] - m1) * inv1 * g.y + bt.y;
            float h2 = (c[nt][2] - m2) * inv2 * g.x + bt.x;
            float h3 = (c[nt][3] - m2) * inv2 * g.y + bt.y;
            unsigned hh, ll;
            split2(make_float2(h0, h1v), hh, ll);
            ea[r1 * EP2 + (col >> 1)] = make_uint2(hh, ll);
            split2(make_float2(h2, h3), hh, ll);
            ea[r2 * EP2 + (col >> 1)] = make_uint2(hh, ll);
        }
    }

    // GEMM2: nh @ nW2 -> out
    zero_c(c);
    gemm_pk(ea, 0, g_nW2p, 8, wb, tid, r1, cbase, gid, tg, c);
    {
        int n1 = n0 + r1, n2 = n0 + r2;
#pragma unroll
        for (int nt = 0; nt < 8; ++nt) {
            int col = cbase + nt * 8 + 2 * tg;
            float2 b = *(const float2*)(nb2 + col);
            if (n1 < N) {
                float2 f = *(const float2*)(feats + (size_t)n1 * 128 + col);
                *(float2*)(out + (size_t)n1 * 128 + col) =
                    make_float2(0.75f * (c[nt][0] + b.x) + 0.25f * f.x,
                                0.75f * (c[nt][1] + b.y) + 0.25f * f.y);
            }
            if (n2 < N) {
                float2 f = *(const float2*)(feats + (size_t)n2 * 128 + col);
                *(float2*)(out + (size_t)n2 * 128 + col) =
                    make_float2(0.75f * (c[nt][2] + b.x) + 0.25f * f.x,
                                0.75f * (c[nt][3] + b.y) + 0.25f * f.y);
            }
        }
    }
    if (tid < TILE) {
        int n = n0 + tid;
        if (n < N) {
            float cnt = g_cnt[n];
            if (cnt < 1.f) cnt = 1.f;
            float inv = 1.f / cnt;
            size_t base = (size_t)N * 128 + (size_t)n * 3;
            out[base + 0] = x[(size_t)n * 3 + 0] + g_xsum[(size_t)n * 3 + 0] * inv;
            out[base + 1] = x[(size_t)n * 3 + 1] + g_xsum[(size_t)n * 3 + 1] * inv;
            out[base + 2] = x[(size_t)n * 3 + 2] + g_xsum[(size_t)n * 3 + 2] * inv;
        }
    }
}

extern "C" void kernel_launch(void* const* d_in, const int* in_sizes, int n_in,
                              void* d_out, int out_size)
{
    const float* feats      = (const float*)d_in[0];
    const float* orig       = (const float*)d_in[1];
    const float* x          = (const float*)d_in[2];
    /* d_in[3] = x_orig, unused (X_CONN_INIT = 0) */
    const float* edge_feats = (const float*)d_in[4];
    const int*   src        = (const int*)d_in[5];
    const int*   dst        = (const int*)d_in[6];
    const float* eW1  = (const float*)d_in[7];
    const float* eb1  = (const float*)d_in[8];
    const float* eg1  = (const float*)d_in[9];
    const float* ebn1 = (const float*)d_in[10];
    const float* eW2  = (const float*)d_in[11];
    const float* eb2  = (const float*)d_in[12];
    const float* nng  = (const float*)d_in[13];
    const float* nnb  = (const float*)d_in[14];
    const float* nW1  = (const float*)d_in[15];
    const float* nb1  = (const float*)d_in[16];
    const float* ng1  = (const float*)d_in[17];
    const float* nbn1 = (const float*)d_in[18];
    const float* nW2  = (const float*)d_in[19];
    const float* nb2  = (const float*)d_in[20];
    const float* cW1  = (const float*)d_in[21];
    const float* cb1  = (const float*)d_in[22];
    const float* cW2  = (const float*)d_in[23];

    const int N = in_sizes[0] / HID;
    const int E = in_sizes[5];

    void *aggr_p, *xs_p, *cnt_p;
    cudaGetSymbolAddress(&aggr_p, g_aggr);
    cudaGetSymbolAddress(&xs_p, g_xsum);
    cudaGetSymbolAddress(&cnt_p, g_cnt);
    cudaMemsetAsync(aggr_p, 0, (size_t)N * OUT * sizeof(float), 0);
    cudaMemsetAsync(xs_p, 0, (size_t)N * 3 * sizeof(float), 0);
    cudaMemsetAsync(cnt_p, 0, (size_t)N * sizeof(float), 0);

    prepack_kernel<<<126, 256>>>(eW1, eW2, cW1, nW1, nW2);

    cudaFuncSetAttribute(edge_kernel, cudaFuncAttributeMaxDynamicSharedMemorySize, SMEM_E);
    cudaFuncSetAttribute(node_kernel, cudaFuncAttributeMaxDynamicSharedMemorySize, SMEM_N);

    int eblocks = (E + TILE - 1) / TILE;
    edge_kernel<<<eblocks, 256, SMEM_E>>>(feats, x, edge_feats, src, dst,
                                          eb1, eg1, ebn1, eb2, cb1, cW2, E);

    int nblocks = (N + TILE - 1) / TILE;
    node_kernel<<<nblocks, 256, SMEM_N>>>(feats, orig, x, nng, nnb,
                                          nb1, ng1, nbn1, nb2,
                                          (float*)d_out, N);
}